// round 2
// baseline (speedup 1.0000x reference)
#include <cuda_runtime.h>
#include <cuda_bf16.h>
#include <mma.h>

using namespace nvcuda;

// Problem constants
#define BB    4
#define NN    2048
#define DIMC  1024
#define HH    16
#define DH    64
#define NOUT  3072            // 3 * HEADS * DIM_HEAD
#define MROWS 8192            // B * N

// 96MB static scratch for the QKV projection result, layout [8192][3072] row-major.
__device__ float g_qkv[(size_t)MROWS * NOUT];

// ---------------------------------------------------------------------------
// Kernel 1: QKV projection GEMM  x[8192,1024] @ w[1024,3072] -> g_qkv
// TF32 wmma, 128x128 block tile, 8 warps (2x4), warp tile 64x32 (4x2 frags).
// ---------------------------------------------------------------------------
__global__ __launch_bounds__(256) void qkv_gemm(const float* __restrict__ x,
                                                const float* __restrict__ w) {
    __shared__ float sA[128 * 36];   // [128][36] pad ld=36
    __shared__ float sB[32 * 132];   // [32][132] pad ld=132

    const int m0 = blockIdx.y * 128;
    const int n0 = blockIdx.x * 128;
    const int tid  = threadIdx.x;
    const int warp = tid >> 5;
    const int wr   = warp >> 2;   // 0..1  (64-row strip)
    const int wc   = warp & 3;    // 0..3  (32-col strip)

    wmma::fragment<wmma::accumulator, 16, 16, 8, float> cf[4][2];
    #pragma unroll
    for (int i = 0; i < 4; i++)
        #pragma unroll
        for (int j = 0; j < 2; j++)
            wmma::fill_fragment(cf[i][j], 0.0f);

    for (int k0 = 0; k0 < DIMC; k0 += 32) {
        // Load A tile: 128 rows x 32 cols = 1024 float4
        #pragma unroll
        for (int it = tid; it < 1024; it += 256) {
            int row = it >> 3, c4 = it & 7;
            float4 v = *(const float4*)(x + (size_t)(m0 + row) * DIMC + k0 + c4 * 4);
            *(float4*)(sA + row * 36 + c4 * 4) = v;
        }
        // Load B tile: 32 rows x 128 cols = 1024 float4
        #pragma unroll
        for (int it = tid; it < 1024; it += 256) {
            int row = it >> 5, c4 = it & 31;
            float4 v = *(const float4*)(w + (size_t)(k0 + row) * NOUT + n0 + c4 * 4);
            *(float4*)(sB + row * 132 + c4 * 4) = v;
        }
        __syncthreads();

        #pragma unroll
        for (int kk = 0; kk < 4; kk++) {
            wmma::fragment<wmma::matrix_a, 16, 16, 8, wmma::precision::tf32, wmma::row_major> af[4];
            wmma::fragment<wmma::matrix_b, 16, 16, 8, wmma::precision::tf32, wmma::row_major> bf[2];
            #pragma unroll
            for (int i = 0; i < 4; i++) {
                wmma::load_matrix_sync(af[i], sA + (wr * 64 + i * 16) * 36 + kk * 8, 36);
                #pragma unroll
                for (int t = 0; t < af[i].num_elements; t++)
                    af[i].x[t] = wmma::__float_to_tf32(af[i].x[t]);
            }
            #pragma unroll
            for (int j = 0; j < 2; j++) {
                wmma::load_matrix_sync(bf[j], sB + (kk * 8) * 132 + wc * 32 + j * 16, 132);
                #pragma unroll
                for (int t = 0; t < bf[j].num_elements; t++)
                    bf[j].x[t] = wmma::__float_to_tf32(bf[j].x[t]);
            }
            #pragma unroll
            for (int i = 0; i < 4; i++)
                #pragma unroll
                for (int j = 0; j < 2; j++)
                    wmma::mma_sync(cf[i][j], af[i], bf[j], cf[i][j]);
        }
        __syncthreads();
    }

    #pragma unroll
    for (int i = 0; i < 4; i++)
        #pragma unroll
        for (int j = 0; j < 2; j++) {
            int row0 = m0 + wr * 64 + i * 16;
            int col0 = n0 + wc * 32 + j * 16;
            wmma::store_matrix_sync(g_qkv + (size_t)row0 * NOUT + col0, cf[i][j],
                                    NOUT, wmma::mem_row_major);
        }
}

// ---------------------------------------------------------------------------
// Kernel 2: flash attention. One block per (q-tile of 64 rows, head, batch).
// 128 threads = 4 warps. Q,K,V tiles gathered directly out of g_qkv.
// Online softmax: 64 row-owner threads keep O[64], m, l in registers.
// ---------------------------------------------------------------------------
#define LDS 68                       // padded leading dim for 64-wide tiles
#define TILE_FLOATS (64 * LDS)

__global__ __launch_bounds__(128) void flash_attn(float* __restrict__ out) {
    extern __shared__ float sm[];
    float* sQ  = sm;                         // 64 x 68
    float* sK  = sQ + TILE_FLOATS;           // 64 x 68  (reused as PV result T)
    float* sV  = sK + TILE_FLOATS;           // 64 x 68
    float* sS  = sV + TILE_FLOATS;           // 64 x 68
    float* sAl = sS + TILE_FLOATS;           // 64

    const int q0  = blockIdx.x * 64;
    const int h   = blockIdx.y;
    const int b   = blockIdx.z;
    const int tid = threadIdx.x;
    const int warp = tid >> 5;

    // Base pointer for this (b, h): Q at +0, K at +1024, V at +2048 columns.
    const float* base = g_qkv + (size_t)(b * NN) * NOUT + h * DH;

    // Load Q tile (64 rows x 64 cols = 1024 float4)
    #pragma unroll
    for (int it = tid; it < 1024; it += 128) {
        int row = it >> 4, c4 = it & 15;
        float4 v = *(const float4*)(base + (size_t)(q0 + row) * NOUT + c4 * 4);
        *(float4*)(sQ + row * LDS + c4 * 4) = v;
    }

    float m_i = -1e30f, l_i = 0.0f;
    float o[64];
    if (tid < 64) {
        #pragma unroll
        for (int c = 0; c < 64; c++) o[c] = 0.0f;
    }
    __syncthreads();

    const float scale = 0.125f;   // 64^-0.5

    for (int j0 = 0; j0 < NN; j0 += 64) {
        // Load K and V tiles
        #pragma unroll
        for (int it = tid; it < 1024; it += 128) {
            int row = it >> 4, c4 = it & 15;
            const float* kp = base + 1024 + (size_t)(j0 + row) * NOUT + c4 * 4;
            const float* vp = base + 2048 + (size_t)(j0 + row) * NOUT + c4 * 4;
            *(float4*)(sK + row * LDS + c4 * 4) = *(const float4*)kp;
            *(float4*)(sV + row * LDS + c4 * 4) = *(const float4*)vp;
        }
        __syncthreads();

        // S = scale * Q @ K^T   (each warp: 16-row strip, 4 col frags)
        {
            wmma::fragment<wmma::accumulator, 16, 16, 8, float> cf[4];
            #pragma unroll
            for (int j = 0; j < 4; j++) wmma::fill_fragment(cf[j], 0.0f);
            #pragma unroll
            for (int kk = 0; kk < 8; kk++) {
                wmma::fragment<wmma::matrix_a, 16, 16, 8, wmma::precision::tf32, wmma::row_major> af;
                wmma::load_matrix_sync(af, sQ + (warp * 16) * LDS + kk * 8, LDS);
                #pragma unroll
                for (int t = 0; t < af.num_elements; t++)
                    af.x[t] = wmma::__float_to_tf32(af.x[t]);
                #pragma unroll
                for (int j = 0; j < 4; j++) {
                    wmma::fragment<wmma::matrix_b, 16, 16, 8, wmma::precision::tf32, wmma::col_major> bf;
                    wmma::load_matrix_sync(bf, sK + (j * 16) * LDS + kk * 8, LDS);
                    #pragma unroll
                    for (int t = 0; t < bf.num_elements; t++)
                        bf.x[t] = wmma::__float_to_tf32(bf.x[t]);
                    wmma::mma_sync(cf[j], af, bf, cf[j]);
                }
            }
            #pragma unroll
            for (int j = 0; j < 4; j++) {
                #pragma unroll
                for (int t = 0; t < cf[j].num_elements; t++) cf[j].x[t] *= scale;
                wmma::store_matrix_sync(sS + (warp * 16) * LDS + j * 16, cf[j],
                                        LDS, wmma::mem_row_major);
            }
        }
        __syncthreads();

        // Online softmax: one thread per row
        if (tid < 64) {
            float* srow = sS + tid * LDS;
            float mx = m_i;
            #pragma unroll
            for (int c = 0; c < 64; c++) mx = fmaxf(mx, srow[c]);
            float alpha = __expf(m_i - mx);
            float sum = 0.0f;
            #pragma unroll
            for (int c = 0; c < 64; c++) {
                float p = __expf(srow[c] - mx);
                srow[c] = p;
                sum += p;
            }
            l_i = l_i * alpha + sum;
            m_i = mx;
            sAl[tid] = alpha;
        }
        __syncthreads();

        // T = P @ V   (result into sK, which is free now)
        {
            wmma::fragment<wmma::accumulator, 16, 16, 8, float> cf[4];
            #pragma unroll
            for (int j = 0; j < 4; j++) wmma::fill_fragment(cf[j], 0.0f);
            #pragma unroll
            for (int kk = 0; kk < 8; kk++) {
                wmma::fragment<wmma::matrix_a, 16, 16, 8, wmma::precision::tf32, wmma::row_major> af;
                wmma::load_matrix_sync(af, sS + (warp * 16) * LDS + kk * 8, LDS);
                #pragma unroll
                for (int t = 0; t < af.num_elements; t++)
                    af.x[t] = wmma::__float_to_tf32(af.x[t]);
                #pragma unroll
                for (int j = 0; j < 4; j++) {
                    wmma::fragment<wmma::matrix_b, 16, 16, 8, wmma::precision::tf32, wmma::row_major> bf;
                    wmma::load_matrix_sync(bf, sV + (kk * 8) * LDS + j * 16, LDS);
                    #pragma unroll
                    for (int t = 0; t < bf.num_elements; t++)
                        bf.x[t] = wmma::__float_to_tf32(bf.x[t]);
                    wmma::mma_sync(cf[j], af, bf, cf[j]);
                }
            }
            #pragma unroll
            for (int j = 0; j < 4; j++)
                wmma::store_matrix_sync(sK + (warp * 16) * LDS + j * 16, cf[j],
                                        LDS, wmma::mem_row_major);
        }
        __syncthreads();

        // O update (registers), one thread per row
        if (tid < 64) {
            float alpha = sAl[tid];
            float* trow = sK + tid * LDS;
            #pragma unroll
            for (int c = 0; c < 64; c++) o[c] = o[c] * alpha + trow[c];
        }
        __syncthreads();
    }

    // Final normalize + write: out[b][n][h*64 + d]
    if (tid < 64) {
        float inv = 1.0f / l_i;
        float* orow = out + (size_t)(b * NN + q0 + tid) * (HH * DH) + h * DH;
        #pragma unroll
        for (int c = 0; c < 64; c += 4) {
            float4 v = make_float4(o[c] * inv, o[c + 1] * inv,
                                   o[c + 2] * inv, o[c + 3] * inv);
            *(float4*)(orow + c) = v;
        }
    }
}

// ---------------------------------------------------------------------------
// Launcher
// ---------------------------------------------------------------------------
extern "C" void kernel_launch(void* const* d_in, const int* in_sizes, int n_in,
                              void* d_out, int out_size) {
    const float* x = (const float*)d_in[0];   // [4, 2048, 1024]
    const float* w = (const float*)d_in[1];   // [1024, 3072]
    float* out = (float*)d_out;               // [4, 2048, 1024]

    // Flash kernel needs 70KB dynamic smem; set limit every call (idempotent,
    // not a stream op, capture-safe).
    const int smem_bytes = (4 * TILE_FLOATS + 64) * (int)sizeof(float);
    cudaFuncSetAttribute(flash_attn, cudaFuncAttributeMaxDynamicSharedMemorySize,
                         smem_bytes);

    dim3 g1(NOUT / 128, MROWS / 128);   // (24, 64)
    qkv_gemm<<<g1, 256>>>(x, w);

    dim3 g2(NN / 64, HH, BB);           // (32, 16, 4)
    flash_attn<<<g2, 128, smem_bytes>>>(out);
}

// round 4
// speedup vs baseline: 2.4075x; 2.4075x over previous
#include <cuda_runtime.h>
#include <cuda_bf16.h>
#include <cstdint>

// Problem constants
#define BB    4
#define NN    2048
#define DIMC  1024
#define HH    16
#define DH    64
#define NOUT  3072            // 3 * HEADS * DIM_HEAD
#define MROWS 8192            // B * N

// 96MB static scratch for the QKV projection result, layout [8192][3072] row-major.
__device__ float g_qkv[(size_t)MROWS * NOUT];

// ---------------------------------------------------------------------------
// PTX helpers
// ---------------------------------------------------------------------------
__device__ __forceinline__ uint32_t f2tf32(float f) {
    uint32_t r;
    asm("cvt.rna.tf32.f32 %0, %1;" : "=r"(r) : "f"(f));
    return r;
}

__device__ __forceinline__ void mma_tf32(float c[4], const uint32_t a[4],
                                         uint32_t b0, uint32_t b1) {
    asm volatile(
        "mma.sync.aligned.m16n8k8.row.col.f32.tf32.tf32.f32 "
        "{%0,%1,%2,%3}, {%4,%5,%6,%7}, {%8,%9}, {%0,%1,%2,%3};"
        : "+f"(c[0]), "+f"(c[1]), "+f"(c[2]), "+f"(c[3])
        : "r"(a[0]), "r"(a[1]), "r"(a[2]), "r"(a[3]), "r"(b0), "r"(b1));
}

__device__ __forceinline__ void cp_async16(void* smem, const void* gmem) {
    uint32_t s = (uint32_t)__cvta_generic_to_shared(smem);
    asm volatile("cp.async.cg.shared.global [%0], [%1], 16;\n" :: "r"(s), "l"(gmem));
}
__device__ __forceinline__ void cp_commit() {
    asm volatile("cp.async.commit_group;\n" ::: "memory");
}
__device__ __forceinline__ void cp_wait1() {
    asm volatile("cp.async.wait_group 1;\n" ::: "memory");
}
__device__ __forceinline__ void cp_wait0() {
    asm volatile("cp.async.wait_group 0;\n" ::: "memory");
}

// ---------------------------------------------------------------------------
// Kernel 1: QKV projection GEMM  x[8192,1024] @ w[1024,3072] -> g_qkv
// TF32 mma via wmma-equivalent tiles, 128x128 block tile, 8 warps,
// cp.async 2-stage pipeline, BK=32.
// ---------------------------------------------------------------------------
#define GA_LD 36
#define GB_LD 132
#define GA_STAGE (128 * GA_LD)   // 4608 floats
#define GB_STAGE (32 * GB_LD)    // 4224 floats

__global__ __launch_bounds__(256) void qkv_gemm(const float* __restrict__ x,
                                                const float* __restrict__ w) {
    extern __shared__ float gsm[];
    float* sA = gsm;                     // 2 stages of 128x36
    float* sB = gsm + 2 * GA_STAGE;      // 2 stages of 32x132

    const int m0 = blockIdx.y * 128;
    const int n0 = blockIdx.x * 128;
    const int tid  = threadIdx.x;
    const int warp = tid >> 5;
    const int lane = tid & 31;
    const int g  = lane >> 2;       // groupID 0..7
    const int tg = lane & 3;        // thread-in-group 0..3
    const int wr = warp >> 2;       // 0..1 (64-row strip)
    const int wc = warp & 3;        // 0..3 (32-col strip)

    // Accumulators: warp tile 64x32 -> rows: 4 m-tiles of 16, cols: 4 n-tiles of 8
    float acc[4][4][4];
    #pragma unroll
    for (int i = 0; i < 4; i++)
        #pragma unroll
        for (int j = 0; j < 4; j++)
            #pragma unroll
            for (int t = 0; t < 4; t++) acc[i][j][t] = 0.0f;

    // async load of one stage
    auto load_stage = [&](int s, int k0) {
        float* sAs = sA + s * GA_STAGE;
        float* sBs = sB + s * GB_STAGE;
        #pragma unroll
        for (int it = tid; it < 1024; it += 256) {
            int row = it >> 3, c4 = it & 7;
            cp_async16(sAs + row * GA_LD + c4 * 4,
                       x + (size_t)(m0 + row) * DIMC + k0 + c4 * 4);
        }
        #pragma unroll
        for (int it = tid; it < 1024; it += 256) {
            int row = it >> 5, c4 = it & 31;
            cp_async16(sBs + row * GB_LD + c4 * 4,
                       w + (size_t)(k0 + row) * NOUT + n0 + c4 * 4);
        }
        cp_commit();
    };

    load_stage(0, 0);
    int buf = 0;

    for (int k0 = 0; k0 < DIMC; k0 += 32) {
        if (k0 + 32 < DIMC) {
            load_stage(buf ^ 1, k0 + 32);
            cp_wait1();
        } else {
            cp_wait0();
        }
        __syncthreads();

        float* sAs = sA + buf * GA_STAGE;
        float* sBs = sB + buf * GB_STAGE;

        #pragma unroll
        for (int kk = 0; kk < 4; kk++) {   // 4 k-chunks of 8
            // A fragments for 4 m-tiles
            uint32_t af[4][4];
            #pragma unroll
            for (int i = 0; i < 4; i++) {
                int r0 = wr * 64 + i * 16;
                const float* p = sAs + (size_t)0;
                af[i][0] = f2tf32(p[(r0 + g)     * GA_LD + kk * 8 + tg]);
                af[i][1] = f2tf32(p[(r0 + g + 8) * GA_LD + kk * 8 + tg]);
                af[i][2] = f2tf32(p[(r0 + g)     * GA_LD + kk * 8 + tg + 4]);
                af[i][3] = f2tf32(p[(r0 + g + 8) * GA_LD + kk * 8 + tg + 4]);
            }
            #pragma unroll
            for (int j = 0; j < 4; j++) {   // 4 n-tiles of 8
                int c0 = wc * 32 + j * 8;
                // B (k x n, col-major fragment): b0 row=tg col=g ; b1 row=tg+4
                uint32_t b0 = f2tf32(sBs[(kk * 8 + tg)     * GB_LD + c0 + g]);
                uint32_t b1 = f2tf32(sBs[(kk * 8 + tg + 4) * GB_LD + c0 + g]);
                #pragma unroll
                for (int i = 0; i < 4; i++)
                    mma_tf32(acc[i][j], af[i], b0, b1);
            }
        }
        __syncthreads();
        buf ^= 1;
    }

    // Epilogue: c0 row=g col=2tg ; c1 col=2tg+1 ; c2/c3 row=g+8
    #pragma unroll
    for (int i = 0; i < 4; i++) {
        int r0 = m0 + wr * 64 + i * 16;
        #pragma unroll
        for (int j = 0; j < 4; j++) {
            int c0 = n0 + wc * 32 + j * 8 + 2 * tg;
            float* p0 = g_qkv + (size_t)(r0 + g) * NOUT + c0;
            float* p1 = g_qkv + (size_t)(r0 + g + 8) * NOUT + c0;
            *(float2*)p0 = make_float2(acc[i][j][0], acc[i][j][1]);
            *(float2*)p1 = make_float2(acc[i][j][2], acc[i][j][3]);
        }
    }
}

// ---------------------------------------------------------------------------
// Kernel 2: flash attention, register-resident FA2.
// Block: 128 q-rows (8 warps x 16 rows), Bc=64, 256 threads.
// cp.async double-buffered K/V. Online softmax fully in registers.
// ---------------------------------------------------------------------------
#define BRQ 128
#define BCK 64
#define LDK 68
#define LDV 72
#define LDP 68
#define K_STAGE (BCK * LDK)   // 4352
#define V_STAGE (BCK * LDV)   // 4608

__global__ __launch_bounds__(256) void flash_attn(float* __restrict__ out) {
    extern __shared__ float fsm[];
    float* sK = fsm;                             // 2 stages
    float* sV = fsm + 2 * K_STAGE;               // 2 stages
    float* sP = fsm + 2 * K_STAGE + 2 * V_STAGE; // 8 warps x 16 x LDP

    const int q0  = blockIdx.x * BRQ;
    const int h   = blockIdx.y;
    const int b   = blockIdx.z;
    const int tid  = threadIdx.x;
    const int warp = tid >> 5;
    const int lane = tid & 31;
    const int g  = lane >> 2;
    const int tg = lane & 3;

    const float* base = g_qkv + (size_t)(b * NN) * NOUT + h * DH;
    const float* kbase = base + 1024;
    const float* vbase = base + 2048;

    // ---- load Q fragments straight from gmem, folding the 1/8 scale ----
    uint32_t qa[8][4];
    {
        const int r0 = q0 + warp * 16;
        #pragma unroll
        for (int kk = 0; kk < 8; kk++) {
            int c = kk * 8 + tg;
            qa[kk][0] = f2tf32(0.125f * base[(size_t)(r0 + g)     * NOUT + c]);
            qa[kk][1] = f2tf32(0.125f * base[(size_t)(r0 + g + 8) * NOUT + c]);
            qa[kk][2] = f2tf32(0.125f * base[(size_t)(r0 + g)     * NOUT + c + 4]);
            qa[kk][3] = f2tf32(0.125f * base[(size_t)(r0 + g + 8) * NOUT + c + 4]);
        }
    }

    float o[8][4];
    #pragma unroll
    for (int dt = 0; dt < 8; dt++)
        #pragma unroll
        for (int t = 0; t < 4; t++) o[dt][t] = 0.0f;
    float m0r = -1e30f, m1r = -1e30f, l0 = 0.0f, l1 = 0.0f;

    // async loader for KV tile j0 into stage s
    auto load_kv = [&](int s, int j0) {
        float* sKs = sK + s * K_STAGE;
        float* sVs = sV + s * V_STAGE;
        #pragma unroll
        for (int it = tid; it < 1024; it += 256) {
            int row = it >> 4, c4 = it & 15;
            cp_async16(sKs + row * LDK + c4 * 4,
                       kbase + (size_t)(j0 + row) * NOUT + c4 * 4);
        }
        #pragma unroll
        for (int it = tid; it < 1024; it += 256) {
            int row = it >> 4, c4 = it & 15;
            cp_async16(sVs + row * LDV + c4 * 4,
                       vbase + (size_t)(j0 + row) * NOUT + c4 * 4);
        }
        cp_commit();
    };

    load_kv(0, 0);
    int buf = 0;

    float* sPw = sP + warp * 16 * LDP;

    for (int j0 = 0; j0 < NN; j0 += BCK) {
        if (j0 + BCK < NN) {
            load_kv(buf ^ 1, j0 + BCK);
            cp_wait1();
        } else {
            cp_wait0();
        }
        __syncthreads();

        float* sKs = sK + buf * K_STAGE;
        float* sVs = sV + buf * V_STAGE;

        // ---- S = (Q*scale) @ K^T : 16 x 64 strip per warp ----
        float s[8][4];
        #pragma unroll
        for (int jt = 0; jt < 8; jt++)
            #pragma unroll
            for (int t = 0; t < 4; t++) s[jt][t] = 0.0f;

        #pragma unroll
        for (int kk = 0; kk < 8; kk++) {
            #pragma unroll
            for (int jt = 0; jt < 8; jt++) {
                // B = K^T chunk (d x j): b0 d=kk*8+tg, j=jt*8+g
                uint32_t b0 = f2tf32(sKs[(jt * 8 + g) * LDK + kk * 8 + tg]);
                uint32_t b1 = f2tf32(sKs[(jt * 8 + g) * LDK + kk * 8 + tg + 4]);
                mma_tf32(s[jt], qa[kk], b0, b1);
            }
        }

        // ---- online softmax in registers (rows g and g+8 of warp strip) ----
        float mx0 = -1e30f, mx1 = -1e30f;
        #pragma unroll
        for (int jt = 0; jt < 8; jt++) {
            mx0 = fmaxf(mx0, fmaxf(s[jt][0], s[jt][1]));
            mx1 = fmaxf(mx1, fmaxf(s[jt][2], s[jt][3]));
        }
        mx0 = fmaxf(mx0, __shfl_xor_sync(0xffffffff, mx0, 1));
        mx0 = fmaxf(mx0, __shfl_xor_sync(0xffffffff, mx0, 2));
        mx1 = fmaxf(mx1, __shfl_xor_sync(0xffffffff, mx1, 1));
        mx1 = fmaxf(mx1, __shfl_xor_sync(0xffffffff, mx1, 2));

        float mn0 = fmaxf(m0r, mx0);
        float mn1 = fmaxf(m1r, mx1);
        float a0 = __expf(m0r - mn0);
        float a1 = __expf(m1r - mn1);

        float sum0 = 0.0f, sum1 = 0.0f;
        #pragma unroll
        for (int jt = 0; jt < 8; jt++) {
            s[jt][0] = __expf(s[jt][0] - mn0);
            s[jt][1] = __expf(s[jt][1] - mn0);
            s[jt][2] = __expf(s[jt][2] - mn1);
            s[jt][3] = __expf(s[jt][3] - mn1);
            sum0 += s[jt][0] + s[jt][1];
            sum1 += s[jt][2] + s[jt][3];
        }
        sum0 += __shfl_xor_sync(0xffffffff, sum0, 1);
        sum0 += __shfl_xor_sync(0xffffffff, sum0, 2);
        sum1 += __shfl_xor_sync(0xffffffff, sum1, 1);
        sum1 += __shfl_xor_sync(0xffffffff, sum1, 2);

        l0 = l0 * a0 + sum0;
        l1 = l1 * a1 + sum1;
        m0r = mn0;
        m1r = mn1;

        #pragma unroll
        for (int dt = 0; dt < 8; dt++) {
            o[dt][0] *= a0; o[dt][1] *= a0;
            o[dt][2] *= a1; o[dt][3] *= a1;
        }

        // ---- P: C-layout regs -> warp-private smem (converted to tf32 bits) ----
        uint32_t* sPu = (uint32_t*)sPw;
        #pragma unroll
        for (int jt = 0; jt < 8; jt++) {
            uint2 v0 = make_uint2(f2tf32(s[jt][0]), f2tf32(s[jt][1]));
            uint2 v1 = make_uint2(f2tf32(s[jt][2]), f2tf32(s[jt][3]));
            *(uint2*)(sPu + g * LDP + jt * 8 + 2 * tg) = v0;
            *(uint2*)(sPu + (g + 8) * LDP + jt * 8 + 2 * tg) = v1;
        }
        __syncwarp();

        // ---- O += P @ V ----
        #pragma unroll
        for (int kk = 0; kk < 8; kk++) {
            uint32_t pa[4];
            pa[0] = sPu[(g)     * LDP + kk * 8 + tg];
            pa[1] = sPu[(g + 8) * LDP + kk * 8 + tg];
            pa[2] = sPu[(g)     * LDP + kk * 8 + tg + 4];
            pa[3] = sPu[(g + 8) * LDP + kk * 8 + tg + 4];
            #pragma unroll
            for (int dt = 0; dt < 8; dt++) {
                uint32_t b0 = f2tf32(sVs[(kk * 8 + tg)     * LDV + dt * 8 + g]);
                uint32_t b1 = f2tf32(sVs[(kk * 8 + tg + 4) * LDV + dt * 8 + g]);
                mma_tf32(o[dt], pa, b0, b1);
            }
        }

        __syncthreads();   // all warps done with sK/sV before next overwrite
        buf ^= 1;
    }

    // ---- epilogue: out[b][n][h*64 + d] ----
    const float inv0 = 1.0f / l0;
    const float inv1 = 1.0f / l1;
    const int r0 = q0 + warp * 16;
    float* ob = out + (size_t)(b * NN) * (HH * DH) + h * DH;
    #pragma unroll
    for (int dt = 0; dt < 8; dt++) {
        int c = dt * 8 + 2 * tg;
        *(float2*)(ob + (size_t)(r0 + g) * (HH * DH) + c) =
            make_float2(o[dt][0] * inv0, o[dt][1] * inv0);
        *(float2*)(ob + (size_t)(r0 + g + 8) * (HH * DH) + c) =
            make_float2(o[dt][2] * inv1, o[dt][3] * inv1);
    }
}

// ---------------------------------------------------------------------------
// Launcher
// ---------------------------------------------------------------------------
extern "C" void kernel_launch(void* const* d_in, const int* in_sizes, int n_in,
                              void* d_out, int out_size) {
    const float* x = (const float*)d_in[0];   // [4, 2048, 1024]
    const float* w = (const float*)d_in[1];   // [1024, 3072]
    float* out = (float*)d_out;               // [4, 2048, 1024]

    const int gemm_smem  = (2 * GA_STAGE + 2 * GB_STAGE) * (int)sizeof(float); // ~70.7KB
    const int flash_smem = (2 * K_STAGE + 2 * V_STAGE + 8 * 16 * LDP) * (int)sizeof(float); // ~106.5KB

    cudaFuncSetAttribute(qkv_gemm, cudaFuncAttributeMaxDynamicSharedMemorySize,
                         gemm_smem);
    cudaFuncSetAttribute(flash_attn, cudaFuncAttributeMaxDynamicSharedMemorySize,
                         flash_smem);

    dim3 g1(NOUT / 128, MROWS / 128);   // (24, 64)
    qkv_gemm<<<g1, 256, gemm_smem>>>(x, w);

    dim3 g2(NN / BRQ, HH, BB);          // (16, 16, 4)
    flash_attn<<<g2, 256, flash_smem>>>(out);
}

// round 5
// speedup vs baseline: 2.6432x; 1.0979x over previous
#include <cuda_runtime.h>
#include <cuda_bf16.h>
#include <cstdint>

// Problem constants
#define BB    4
#define NN    2048
#define DIMC  1024
#define HH    16
#define DH    64
#define NOUT  3072            // 3 * HEADS * DIM_HEAD
#define MROWS 8192            // B * N
#define XN    ((size_t)BB * NN * DIMC)     // 8388608
#define WN    ((size_t)DIMC * NOUT)        // 3145728

// Static scratch: qkv result (tf32 bits), tf32-converted inputs.
__device__ float g_qkv[(size_t)MROWS * NOUT];
__device__ float g_xt[XN];
__device__ float g_wt[WN];

// ---------------------------------------------------------------------------
// PTX helpers
// ---------------------------------------------------------------------------
__device__ __forceinline__ uint32_t f2tf32(float f) {
    uint32_t r;
    asm("cvt.rna.tf32.f32 %0, %1;" : "=r"(r) : "f"(f));
    return r;
}

__device__ __forceinline__ void mma_tf32(float c[4], const uint32_t a[4],
                                         uint32_t b0, uint32_t b1) {
    asm volatile(
        "mma.sync.aligned.m16n8k8.row.col.f32.tf32.tf32.f32 "
        "{%0,%1,%2,%3}, {%4,%5,%6,%7}, {%8,%9}, {%0,%1,%2,%3};"
        : "+f"(c[0]), "+f"(c[1]), "+f"(c[2]), "+f"(c[3])
        : "r"(a[0]), "r"(a[1]), "r"(a[2]), "r"(a[3]), "r"(b0), "r"(b1));
}

// ldmatrix x4: loads a 16-row x 8-float A-tile (as 4 8x8 b16 matrices).
// Caller supplies the per-lane address. Output order: r0=a0, r1=a2, r2=a1, r3=a3.
__device__ __forceinline__ void ldm_x4(uint32_t& r0, uint32_t& r1,
                                       uint32_t& r2, uint32_t& r3,
                                       const void* p) {
    uint32_t a = (uint32_t)__cvta_generic_to_shared(p);
    asm volatile("ldmatrix.sync.aligned.m8n8.x4.shared.b16 {%0,%1,%2,%3}, [%4];"
                 : "=r"(r0), "=r"(r1), "=r"(r2), "=r"(r3) : "r"(a));
}

__device__ __forceinline__ void cp_async16(void* smem, const void* gmem) {
    uint32_t s = (uint32_t)__cvta_generic_to_shared(smem);
    asm volatile("cp.async.cg.shared.global [%0], [%1], 16;\n" :: "r"(s), "l"(gmem));
}
__device__ __forceinline__ void cp_commit() {
    asm volatile("cp.async.commit_group;\n" ::: "memory");
}
__device__ __forceinline__ void cp_wait1() {
    asm volatile("cp.async.wait_group 1;\n" ::: "memory");
}
__device__ __forceinline__ void cp_wait0() {
    asm volatile("cp.async.wait_group 0;\n" ::: "memory");
}

// ---------------------------------------------------------------------------
// Kernel 0: round x and w to tf32 once.
// ---------------------------------------------------------------------------
__global__ __launch_bounds__(256) void cvt_inputs(const float* __restrict__ x,
                                                  const float* __restrict__ w) {
    const size_t stride = (size_t)gridDim.x * blockDim.x;
    size_t i0 = (size_t)blockIdx.x * blockDim.x + threadIdx.x;
    for (size_t i = i0; i < XN / 4; i += stride) {
        float4 v = *((const float4*)x + i);
        uint4 r;
        r.x = f2tf32(v.x); r.y = f2tf32(v.y); r.z = f2tf32(v.z); r.w = f2tf32(v.w);
        *((uint4*)g_xt + i) = r;
    }
    for (size_t i = i0; i < WN / 4; i += stride) {
        float4 v = *((const float4*)w + i);
        uint4 r;
        r.x = f2tf32(v.x); r.y = f2tf32(v.y); r.z = f2tf32(v.z); r.w = f2tf32(v.w);
        *((uint4*)g_wt + i) = r;
    }
}

// ---------------------------------------------------------------------------
// Kernel 1: QKV projection GEMM  xt[8192,1024] @ wt[1024,3072] -> g_qkv (tf32)
// 128x128 block tile, 8 warps (warp tile 64x32), cp.async 2-stage, BK=32.
// A fragments via ldmatrix.x4; no cvt anywhere in the loop.
// ---------------------------------------------------------------------------
#define GA_LD 36
#define GB_LD 132
#define GA_STAGE (128 * GA_LD)
#define GB_STAGE (32 * GB_LD)

__global__ __launch_bounds__(256) void qkv_gemm(const float* __restrict__ x,
                                                const float* __restrict__ w) {
    extern __shared__ float gsm[];
    float* sA = gsm;
    float* sB = gsm + 2 * GA_STAGE;

    const int m0 = blockIdx.y * 128;
    const int n0 = blockIdx.x * 128;
    const int tid  = threadIdx.x;
    const int warp = tid >> 5;
    const int lane = tid & 31;
    const int g  = lane >> 2;
    const int tg = lane & 3;
    const int wr = warp >> 2;
    const int wc = warp & 3;

    // ldmatrix per-lane row/col offsets (within a 16x8 A tile)
    const int lm_row = (lane & 7) + ((lane >> 4) << 3);   // +8 for matrices 2,3
    const int lm_col = ((lane >> 3) & 1) << 2;            // +4 floats for matrices 1,3

    float acc[4][4][4];
    #pragma unroll
    for (int i = 0; i < 4; i++)
        #pragma unroll
        for (int j = 0; j < 4; j++)
            #pragma unroll
            for (int t = 0; t < 4; t++) acc[i][j][t] = 0.0f;

    auto load_stage = [&](int s, int k0) {
        float* sAs = sA + s * GA_STAGE;
        float* sBs = sB + s * GB_STAGE;
        #pragma unroll
        for (int it = tid; it < 1024; it += 256) {
            int row = it >> 3, c4 = it & 7;
            cp_async16(sAs + row * GA_LD + c4 * 4,
                       x + (size_t)(m0 + row) * DIMC + k0 + c4 * 4);
        }
        #pragma unroll
        for (int it = tid; it < 1024; it += 256) {
            int row = it >> 5, c4 = it & 31;
            cp_async16(sBs + row * GB_LD + c4 * 4,
                       w + (size_t)(k0 + row) * NOUT + n0 + c4 * 4);
        }
        cp_commit();
    };

    load_stage(0, 0);
    int buf = 0;

    for (int k0 = 0; k0 < DIMC; k0 += 32) {
        if (k0 + 32 < DIMC) {
            load_stage(buf ^ 1, k0 + 32);
            cp_wait1();
        } else {
            cp_wait0();
        }
        __syncthreads();

        float* sAs = sA + buf * GA_STAGE;
        const uint32_t* sBu = (const uint32_t*)(sB + buf * GB_STAGE);

        #pragma unroll
        for (int kk = 0; kk < 4; kk++) {
            uint32_t af[4][4];
            #pragma unroll
            for (int i = 0; i < 4; i++) {
                const float* p = sAs + (wr * 64 + i * 16 + lm_row) * GA_LD
                                      + kk * 8 + lm_col;
                ldm_x4(af[i][0], af[i][2], af[i][1], af[i][3], p);
            }
            #pragma unroll
            for (int j = 0; j < 4; j++) {
                int c0 = wc * 32 + j * 8;
                uint32_t b0 = sBu[(kk * 8 + tg)     * GB_LD + c0 + g];
                uint32_t b1 = sBu[(kk * 8 + tg + 4) * GB_LD + c0 + g];
                #pragma unroll
                for (int i = 0; i < 4; i++)
                    mma_tf32(acc[i][j], af[i], b0, b1);
            }
        }
        __syncthreads();
        buf ^= 1;
    }

    // Epilogue: round to tf32 and store bits.
    #pragma unroll
    for (int i = 0; i < 4; i++) {
        int r0 = m0 + wr * 64 + i * 16;
        #pragma unroll
        for (int j = 0; j < 4; j++) {
            int c0 = n0 + wc * 32 + j * 8 + 2 * tg;
            uint32_t* p0 = (uint32_t*)g_qkv + (size_t)(r0 + g) * NOUT + c0;
            uint32_t* p1 = (uint32_t*)g_qkv + (size_t)(r0 + g + 8) * NOUT + c0;
            *(uint2*)p0 = make_uint2(f2tf32(acc[i][j][0]), f2tf32(acc[i][j][1]));
            *(uint2*)p1 = make_uint2(f2tf32(acc[i][j][2]), f2tf32(acc[i][j][3]));
        }
    }
}

// ---------------------------------------------------------------------------
// Kernel 2: flash attention. 4 warps x 32 q-rows (2 m-tiles per warp), Bc=64.
// Q fragments in registers; K/V double-buffered cp.async, raw tf32 bits.
// P staged per-warp in smem, re-read via ldmatrix.
// ---------------------------------------------------------------------------
#define BRQ 128
#define BCK 64
#define LDK 68
#define LDV 72
#define LDP 68
#define K_STAGE (BCK * LDK)
#define V_STAGE (BCK * LDV)

__global__ __launch_bounds__(128) void flash_attn(float* __restrict__ out) {
    extern __shared__ float fsm[];
    float* sK = fsm;                              // 2 stages 64x68
    float* sV = fsm + 2 * K_STAGE;                // 2 stages 64x72
    float* sP = fsm + 2 * K_STAGE + 2 * V_STAGE;  // 4 warps x 32 x 68

    const int q0  = blockIdx.x * BRQ;
    const int h   = blockIdx.y;
    const int b   = blockIdx.z;
    const int tid  = threadIdx.x;
    const int warp = tid >> 5;
    const int lane = tid & 31;
    const int g  = lane >> 2;
    const int tg = lane & 3;

    const int lm_row = (lane & 7) + ((lane >> 4) << 3);
    const int lm_col = ((lane >> 3) & 1) << 2;

    const float* base  = g_qkv + (size_t)(b * NN) * NOUT + h * DH;
    const float* kbase = base + 1024;
    const float* vbase = base + 2048;

    // ---- Q fragments in regs: values are tf32 already; *0.125 is exact ----
    uint32_t qa[2][8][4];
    {
        const int r0 = q0 + warp * 32;
        #pragma unroll
        for (int mt = 0; mt < 2; mt++)
            #pragma unroll
            for (int kk = 0; kk < 8; kk++) {
                int c = kk * 8 + tg;
                const float* pr0 = base + (size_t)(r0 + mt * 16 + g) * NOUT;
                const float* pr1 = base + (size_t)(r0 + mt * 16 + g + 8) * NOUT;
                qa[mt][kk][0] = __float_as_uint(0.125f * pr0[c]);
                qa[mt][kk][1] = __float_as_uint(0.125f * pr1[c]);
                qa[mt][kk][2] = __float_as_uint(0.125f * pr0[c + 4]);
                qa[mt][kk][3] = __float_as_uint(0.125f * pr1[c + 4]);
            }
    }

    float o[2][8][4];
    #pragma unroll
    for (int mt = 0; mt < 2; mt++)
        #pragma unroll
        for (int dt = 0; dt < 8; dt++)
            #pragma unroll
            for (int t = 0; t < 4; t++) o[mt][dt][t] = 0.0f;
    float m_[2][2], l_[2][2];
    #pragma unroll
    for (int mt = 0; mt < 2; mt++) {
        m_[mt][0] = m_[mt][1] = -1e30f;
        l_[mt][0] = l_[mt][1] = 0.0f;
    }

    auto load_kv = [&](int s, int j0) {
        float* sKs = sK + s * K_STAGE;
        float* sVs = sV + s * V_STAGE;
        #pragma unroll
        for (int it = tid; it < 1024; it += 128) {
            int row = it >> 4, c4 = it & 15;
            cp_async16(sKs + row * LDK + c4 * 4,
                       kbase + (size_t)(j0 + row) * NOUT + c4 * 4);
        }
        #pragma unroll
        for (int it = tid; it < 1024; it += 128) {
            int row = it >> 4, c4 = it & 15;
            cp_async16(sVs + row * LDV + c4 * 4,
                       vbase + (size_t)(j0 + row) * NOUT + c4 * 4);
        }
        cp_commit();
    };

    load_kv(0, 0);
    int buf = 0;

    uint32_t* sPu = (uint32_t*)(sP + warp * 32 * LDP);

    for (int j0 = 0; j0 < NN; j0 += BCK) {
        if (j0 + BCK < NN) {
            load_kv(buf ^ 1, j0 + BCK);
            cp_wait1();
        } else {
            cp_wait0();
        }
        __syncthreads();

        const uint32_t* sKu = (const uint32_t*)(sK + buf * K_STAGE);
        const uint32_t* sVu = (const uint32_t*)(sV + buf * V_STAGE);

        // ---- S = (Q*scale) @ K^T : two 16x64 strips per warp ----
        float s[2][8][4];
        #pragma unroll
        for (int mt = 0; mt < 2; mt++)
            #pragma unroll
            for (int jt = 0; jt < 8; jt++)
                #pragma unroll
                for (int t = 0; t < 4; t++) s[mt][jt][t] = 0.0f;

        #pragma unroll
        for (int kk = 0; kk < 8; kk++) {
            #pragma unroll
            for (int jt = 0; jt < 8; jt++) {
                uint32_t b0 = sKu[(jt * 8 + g) * LDK + kk * 8 + tg];
                uint32_t b1 = sKu[(jt * 8 + g) * LDK + kk * 8 + tg + 4];
                mma_tf32(s[0][jt], qa[0][kk], b0, b1);
                mma_tf32(s[1][jt], qa[1][kk], b0, b1);
            }
        }

        // ---- online softmax (register-resident) ----
        #pragma unroll
        for (int mt = 0; mt < 2; mt++) {
            float mx0 = -1e30f, mx1 = -1e30f;
            #pragma unroll
            for (int jt = 0; jt < 8; jt++) {
                mx0 = fmaxf(mx0, fmaxf(s[mt][jt][0], s[mt][jt][1]));
                mx1 = fmaxf(mx1, fmaxf(s[mt][jt][2], s[mt][jt][3]));
            }
            mx0 = fmaxf(mx0, __shfl_xor_sync(0xffffffff, mx0, 1));
            mx0 = fmaxf(mx0, __shfl_xor_sync(0xffffffff, mx0, 2));
            mx1 = fmaxf(mx1, __shfl_xor_sync(0xffffffff, mx1, 1));
            mx1 = fmaxf(mx1, __shfl_xor_sync(0xffffffff, mx1, 2));

            float mn0 = fmaxf(m_[mt][0], mx0);
            float mn1 = fmaxf(m_[mt][1], mx1);
            float a0 = __expf(m_[mt][0] - mn0);
            float a1 = __expf(m_[mt][1] - mn1);

            float sum0 = 0.0f, sum1 = 0.0f;
            #pragma unroll
            for (int jt = 0; jt < 8; jt++) {
                s[mt][jt][0] = __expf(s[mt][jt][0] - mn0);
                s[mt][jt][1] = __expf(s[mt][jt][1] - mn0);
                s[mt][jt][2] = __expf(s[mt][jt][2] - mn1);
                s[mt][jt][3] = __expf(s[mt][jt][3] - mn1);
                sum0 += s[mt][jt][0] + s[mt][jt][1];
                sum1 += s[mt][jt][2] + s[mt][jt][3];
            }
            sum0 += __shfl_xor_sync(0xffffffff, sum0, 1);
            sum0 += __shfl_xor_sync(0xffffffff, sum0, 2);
            sum1 += __shfl_xor_sync(0xffffffff, sum1, 1);
            sum1 += __shfl_xor_sync(0xffffffff, sum1, 2);

            l_[mt][0] = l_[mt][0] * a0 + sum0;
            l_[mt][1] = l_[mt][1] * a1 + sum1;
            m_[mt][0] = mn0;
            m_[mt][1] = mn1;

            #pragma unroll
            for (int dt = 0; dt < 8; dt++) {
                o[mt][dt][0] *= a0; o[mt][dt][1] *= a0;
                o[mt][dt][2] *= a1; o[mt][dt][3] *= a1;
            }
        }

        // ---- P: C-layout regs -> warp-private smem (tf32 bits) ----
        #pragma unroll
        for (int mt = 0; mt < 2; mt++)
            #pragma unroll
            for (int jt = 0; jt < 8; jt++) {
                *(uint2*)(sPu + (mt * 16 + g) * LDP + jt * 8 + 2 * tg) =
                    make_uint2(f2tf32(s[mt][jt][0]), f2tf32(s[mt][jt][1]));
                *(uint2*)(sPu + (mt * 16 + g + 8) * LDP + jt * 8 + 2 * tg) =
                    make_uint2(f2tf32(s[mt][jt][2]), f2tf32(s[mt][jt][3]));
            }
        __syncwarp();

        // ---- O += P @ V ----
        #pragma unroll
        for (int kk = 0; kk < 8; kk++) {
            uint32_t pa0[4], pa1[4];
            ldm_x4(pa0[0], pa0[2], pa0[1], pa0[3],
                   (const float*)sPu + (lm_row) * LDP + kk * 8 + lm_col);
            ldm_x4(pa1[0], pa1[2], pa1[1], pa1[3],
                   (const float*)sPu + (16 + lm_row) * LDP + kk * 8 + lm_col);
            #pragma unroll
            for (int dt = 0; dt < 8; dt++) {
                uint32_t b0 = sVu[(kk * 8 + tg)     * LDV + dt * 8 + g];
                uint32_t b1 = sVu[(kk * 8 + tg + 4) * LDV + dt * 8 + g];
                mma_tf32(o[0][dt], pa0, b0, b1);
                mma_tf32(o[1][dt], pa1, b0, b1);
            }
        }

        __syncwarp();      // done with sPu before next iter's stores
        __syncthreads();   // done with sK/sV before overwrite
        buf ^= 1;
    }

    // ---- epilogue ----
    const int r0 = q0 + warp * 32;
    float* ob = out + (size_t)(b * NN) * (HH * DH) + h * DH;
    #pragma unroll
    for (int mt = 0; mt < 2; mt++) {
        float inv0 = 1.0f / l_[mt][0];
        float inv1 = 1.0f / l_[mt][1];
        #pragma unroll
        for (int dt = 0; dt < 8; dt++) {
            int c = dt * 8 + 2 * tg;
            *(float2*)(ob + (size_t)(r0 + mt * 16 + g) * (HH * DH) + c) =
                make_float2(o[mt][dt][0] * inv0, o[mt][dt][1] * inv0);
            *(float2*)(ob + (size_t)(r0 + mt * 16 + g + 8) * (HH * DH) + c) =
                make_float2(o[mt][dt][2] * inv1, o[mt][dt][3] * inv1);
        }
    }
}

// ---------------------------------------------------------------------------
// Launcher
// ---------------------------------------------------------------------------
extern "C" void kernel_launch(void* const* d_in, const int* in_sizes, int n_in,
                              void* d_out, int out_size) {
    const float* x = (const float*)d_in[0];   // [4, 2048, 1024]
    const float* w = (const float*)d_in[1];   // [1024, 3072]
    float* out = (float*)d_out;               // [4, 2048, 1024]

    const int gemm_smem  = (2 * GA_STAGE + 2 * GB_STAGE) * (int)sizeof(float);
    const int flash_smem = (2 * K_STAGE + 2 * V_STAGE + 4 * 32 * LDP) * (int)sizeof(float);

    cudaFuncSetAttribute(qkv_gemm, cudaFuncAttributeMaxDynamicSharedMemorySize,
                         gemm_smem);
    cudaFuncSetAttribute(flash_attn, cudaFuncAttributeMaxDynamicSharedMemorySize,
                         flash_smem);

    float* xt;
    float* wt;
    cudaGetSymbolAddress((void**)&xt, g_xt);
    cudaGetSymbolAddress((void**)&wt, g_wt);

    cvt_inputs<<<1024, 256>>>(x, w);

    dim3 g1(NOUT / 128, MROWS / 128);   // (24, 64)
    qkv_gemm<<<g1, 256, gemm_smem>>>(xt, wt);

    dim3 g2(NN / BRQ, HH, BB);          // (16, 16, 4)
    flash_attn<<<g2, 128, flash_smem>>>(out);
}